// round 16
// baseline (speedup 1.0000x reference)
#include <cuda_runtime.h>
#include <math.h>

// ---- ANI-1x constants ----
#define RCR 5.2f
#define RCA 3.5f
#define ETA_R 16.0f
#define ETA_A 8.0f
#define PI_F 3.14159265358979323846f
#define AEV_W 384
#define CHUNKS 8          // CTAs per atom
#define BLK 128           // threads per CTA (4 warps)
#define NWC 4             // warps per CTA
#define GWARPS 32         // CHUNKS*NWC warps cooperating per atom
#define NBMAX 256
// build supports n <= 512 (4 rounds of 128)

// Gaussian recurrence over the 4 equally spaced ShfA (0.9,1.55,2.2,2.85; delta=0.65):
// e_a = e0 * r^a * q^(a^2),  r = exp(2*eta*delta*t0), q = exp(-eta*delta^2)
#define QA   0.03404745f      // exp(-8*0.65^2)
#define QA2  0.001159229f     // QA^2
#define TWO_ETA_D 10.4f       // 2*8*0.65

// ShfZ = (2k+1)*pi/16 -> cos/sin are exact constants
__constant__ float c_cz[8]  = { 0.98078528f,  0.83146961f,  0.55557023f,  0.19509032f,
                               -0.19509032f, -0.55557023f, -0.83146961f, -0.98078528f};
__constant__ float c_sz[8]  = { 0.19509032f,  0.55557023f,  0.83146961f,  0.98078528f,
                                0.98078528f,  0.83146961f,  0.55557023f,  0.19509032f};

__global__ void zero_kernel(float4* __restrict__ out4, int n4) {
    int t = blockIdx.x * blockDim.x + threadIdx.x;
    if (t < n4) out4[t] = make_float4(0.f, 0.f, 0.f, 0.f);
}

__global__ __launch_bounds__(BLK, 10)
void aev_kernel(const float* __restrict__ coords, float* __restrict__ out, int n) {
    const int chunk = blockIdx.x & (CHUNKS - 1);
    const int i     = blockIdx.x >> 3;
    const int tid   = threadIdx.x;
    const int lane  = tid & 31;
    const int wl    = tid >> 5;           // warp within CTA: 0..3

    __shared__ float4 s_nbr[NBMAX];       // RCA neighbor (ux,uy,uz,d)
    __shared__ float  s_fcA[NBMAX];       // fc(RCA)
    __shared__ float2 s_rad[NBMAX];       // RCR neighbor (d, 0.25*fc_r)  [chunk 0 only]
    __shared__ int    s_cntA[16], s_cntR[16];
    __shared__ int    s_MA, s_MR;
    __shared__ float  sm_red[NWC][16];
    __shared__ float  sm_ang[NWC][32];

    const float cix = coords[3 * i + 0];
    const float ciy = coords[3 * i + 1];
    const float ciz = coords[3 * i + 2];

    if (tid < 16) { s_cntA[tid] = 0; s_cntR[tid] = 0; }
    __syncthreads();

    const int rounds = (n + BLK - 1) / BLK;

    // ---- pass 1: per-(round, warp) counts (deterministic across sibling chunks) ----
    for (int it = 0; it < rounds; it++) {
        int j = it * BLK + tid;
        bool inA = false, inR = false;
        if (j < n && j != i) {
            float dx = cix - coords[3 * j + 0];
            float dy = ciy - coords[3 * j + 1];
            float dz = ciz - coords[3 * j + 2];
            float d2 = dx * dx + dy * dy + dz * dz;
            inR = (d2 <= RCR * RCR);
            inA = (d2 <= RCA * RCA);
        }
        unsigned bA = __ballot_sync(0xFFFFFFFFu, inA);
        unsigned bR = __ballot_sync(0xFFFFFFFFu, inR);
        if (lane == 0) {
            s_cntA[it * NWC + wl] = __popc(bA);
            s_cntR[it * NWC + wl] = __popc(bR);
        }
    }
    __syncthreads();
    if (wl == 0) {   // dual 16-wide segmented exclusive scan
        int l16 = lane & 15;
        int c = (lane < 16) ? s_cntA[l16] : s_cntR[l16];
        int s = c;
        #pragma unroll
        for (int o = 1; o < 16; o <<= 1) {
            int t = __shfl_up_sync(0xFFFFFFFFu, s, o, 16);
            if (l16 >= o) s += t;
        }
        if (lane < 16) { s_cntA[l16] = s - c; if (l16 == 15) s_MA = s; }
        else           { s_cntR[l16] = s - c; if (l16 == 15) s_MR = s; }
    }
    __syncthreads();
    const int M  = s_MA;
    const int MR = s_MR;

    // ---- pass 2: write compacted lists in deterministic j-order ----
    for (int it = 0; it < rounds; it++) {
        int j = it * BLK + tid;
        bool inA = false, inR = false;
        float dx = 0.f, dy = 0.f, dz = 0.f, d2 = 1.f;
        if (j < n && j != i) {
            dx = cix - coords[3 * j + 0];
            dy = ciy - coords[3 * j + 1];
            dz = ciz - coords[3 * j + 2];
            d2 = dx * dx + dy * dy + dz * dz;
            inR = (d2 <= RCR * RCR);
            inA = (d2 <= RCA * RCA);
        }
        unsigned bA = __ballot_sync(0xFFFFFFFFu, inA);
        unsigned bR = __ballot_sync(0xFFFFFFFFu, inR);
        unsigned lml = (1u << lane) - 1u;
        if (inR) {
            float d = sqrtf(d2);
            if (chunk == 0) {   // radial list only needed by chunk 0
                int idxR = s_cntR[it * NWC + wl] + __popc(bR & lml);
                float fc025 = 0.25f * (0.5f * __cosf(PI_F * (1.0f / RCR) * d) + 0.5f);
                s_rad[idxR] = make_float2(d, fc025);
            }
            if (inA) {
                int idxA = s_cntA[it * NWC + wl] + __popc(bA & lml);
                float inv = 1.0f / d;
                s_nbr[idxA] = make_float4(dx * inv, dy * inv, dz * inv, d);
                s_fcA[idxA] = 0.5f * __cosf(PI_F * (1.0f / RCA) * d) + 0.5f;
            }
        }
    }
    __syncthreads();

    // ---- radial (chunk 0 only): bin-per-lane, 2 j's per warp-iter ----
    if (chunk == 0) {
        const int h = lane >> 4;
        const float shr = 0.9f + 0.26875f * (float)(lane & 15);
        float racc = 0.f;
        for (int it = 0; it * 2 * NWC < MR; it++) {
            int j = (2 * it + h) * NWC + wl;
            bool v = (j < MR);
            float2 R = s_rad[v ? j : 0];
            float t = R.x - shr;
            float e = R.y * __expf(-ETA_R * t * t);
            racc += v ? e : 0.f;
        }
        racc += __shfl_xor_sync(0xFFFFFFFFu, racc, 16);
        if (lane < 16) sm_red[wl][lane] = racc;
    }

    // ---- angular: snake rows over 32 global warp-slots; 4 pairs/iter (pg = lane>>3),
    //      8 zeta-bins/group, 4 ShfA accumulators per lane ----
    {
        const int ww = chunk * NWC + wl;         // global warp slot 0..31 for this atom
        const int pg = lane >> 3;
        const int z  = lane & 7;
        const float czL = c_cz[z];
        const float szL = c_sz[z];
        float a0 = 0.f, a1 = 0.f, a2 = 0.f, a3 = 0.f;

        for (int r = 0;; r++) {
            int off = (r & 1) ? (GWARPS - 1 - ww) : ww;
            int v = r * GWARPS + off;
            int jj = M - 1 - v;
            if (jj < 1) break;                   // later rounds only shrink jj
            float4 J = s_nbr[jj];
            float jfc = s_fcA[jj];
            for (int kb = 0; kb < jj; kb += 4) {
                int kk = kb + pg;
                bool ok = (kk < jj);
                int kc = ok ? kk : 0;
                float4 K = s_nbr[kc];
                float g = ok ? (jfc * s_fcA[kc]) : 0.f;
                float ct = 0.95f * (J.x * K.x + J.y * K.y + J.z * K.z);
                float st = sqrtf(fmaxf(1.0f - ct * ct, 0.0f));   // sin(acos(ct)) >= 0
                float davg = 0.5f * (J.w + K.w);
                // cos(theta - ShfZ) = ct*cos + st*sin; x = (1+cos)/2; x^32 by squaring
                float x = 0.5f + 0.5f * (ct * czL + st * szL);
                float x2 = x * x, x4 = x2 * x2, x8 = x4 * x4, x16 = x8 * x8;
                g *= x16 * x16;                                  // fcp * x^32
                // 4 Gaussians from 2 exps via the recurrence
                float t0 = davg - 0.9f;
                float e0 = __expf(-ETA_A * t0 * t0);
                float rr = __expf(TWO_ETA_D * t0);
                float m1 = rr * QA;
                float e1 = e0 * m1;
                float m2 = m1 * QA2;
                float e2 = e1 * m2;
                float m3 = m2 * QA2;
                float e3 = e2 * m3;
                a0 += g * e0;
                a1 += g * e1;
                a2 += g * e2;
                a3 += g * e3;
            }
        }

        // fold the 4 pair-groups; lanes 0-7 then hold bins (a, z=lane)
        #define FOLD(v) v += __shfl_xor_sync(0xFFFFFFFFu, v, 8); \
                        v += __shfl_xor_sync(0xFFFFFFFFu, v, 16);
        FOLD(a0) FOLD(a1) FOLD(a2) FOLD(a3)
        #undef FOLD
        if (lane < 8) {
            sm_ang[wl][0  + lane] = a0;
            sm_ang[wl][8  + lane] = a1;
            sm_ang[wl][16 + lane] = a2;
            sm_ang[wl][24 + lane] = a3;
        }
    }
    __syncthreads();

    // ---- CTA epilogue: gather 4 warps' partials, push to global ----
    if (wl == 0) {
        float v = sm_ang[0][lane] + sm_ang[1][lane] + sm_ang[2][lane] + sm_ang[3][lane];
        if (v != 0.f)
            atomicAdd(&out[i * AEV_W + 64 + lane], 2.0f * v);   // ordered = 2 * (j<k)
    }
    if (chunk == 0 && wl == 1 && lane < 16) {
        float v = sm_red[0][lane] + sm_red[1][lane] + sm_red[2][lane] + sm_red[3][lane];
        out[i * AEV_W + lane] = v;    // plain store over the zeroed base
    }
}

extern "C" void kernel_launch(void* const* d_in, const int* in_sizes, int n_in,
                              void* d_out, int out_size) {
    const float* coords = (const float*)d_in[0];
    float* out = (float*)d_out;
    int n = in_sizes[0] / 3;
    int n4 = out_size / 4;   // 384 % 4 == 0
    zero_kernel<<<(n4 + 255) / 256, 256>>>((float4*)d_out, n4);
    aev_kernel<<<n * CHUNKS, BLK>>>(coords, out, n);
}